// round 15
// baseline (speedup 1.0000x reference)
#include <cuda_runtime.h>
#include <math.h>
#include <stdint.h>

// ---------------- problem constants ----------------
#define LQ   4096
#define NBAT 32
#define M1   (NBAT*LQ)
#define DI   128
#define DS   16
#define NCH  32
#define CLEN (LQ/NCH)
#define M2   (8*LQ)

// ---------------- scratch ----------------
__device__ float g_xi  [(size_t)M1*64];
__device__ float g_xc  [(size_t)M1*DI];
__device__ float g_z   [(size_t)M1*DI];
__device__ float g_u   [(size_t)M1*DI];
__device__ float g_dt  [(size_t)M1*DI];
__device__ __align__(16) float g_bc [(size_t)M1*32];
__device__ float g_y   [(size_t)M1*DI];
__device__ float g_lnb [(size_t)M1*64];
__device__ float g_inter[(size_t)M2*256];
__device__ float g_cv  [(size_t)M2*256];
__device__ float g_P   [NBAT*NCH*DI*DS];
__device__ float g_hend[NBAT*NCH*DI*DS];
__device__ float g_hin [NBAT*NCH*DI*DS];
__device__ float g_Aa  [DI*DS];
__device__ float g_wp  [256*256];
__device__ float g_w2  [160*128];
__device__ float g_ps  [512*256];
__device__ float g_pq  [512*256];
__device__ float g_bnA [256];
__device__ float g_bnB [256];
__device__ int   g_fastA;

// ---------------- prep ----------------
__global__ void k_prep(const float* __restrict__ A_log,
                       const float* __restrict__ oc_w) {
    int i = blockIdx.x * blockDim.x + threadIdx.x;
    if (i < DI*DS) g_Aa[i] = -expf(A_log[i]);
    if (i < 256*256) {
        int o = i >> 8, c = i & 255;
        int dm = c >> 2, ch = c & 3;
        g_wp[o*256 + ch*64 + dm] = oc_w[i];
    }
}

__global__ void k_prep2(const float* __restrict__ xw,
                        const float* __restrict__ dtw) {
    int i = blockIdx.x * 256 + threadIdx.x;
    if (i >= 160*128) return;
    int row = i >> 7, k = i & 127;
    if (row < 32) {
        g_w2[i] = xw[(4 + row)*128 + k];
    } else {
        int d = row - 32;
        float s = 0.f;
        #pragma unroll
        for (int r = 0; r < 4; ++r) s = fmaf(dtw[d*4 + r], xw[r*128 + k], s);
        g_w2[i] = s;
    }
}

__global__ void k_checkA() {
    __shared__ int ok;
    if (threadIdx.x == 0) ok = 1;
    __syncthreads();
    for (int i = threadIdx.x; i < DI*DS; i += 256) {
        int d = i >> 4, s = i & 15;
        float a0  = g_Aa[d*16];
        float ref = (float)(s + 1) * a0;
        if (fabsf(g_Aa[i] - ref) > 1e-4f * fabsf(ref) + 1e-6f) atomicAnd(&ok, 0);
    }
    __syncthreads();
    if (threadIdx.x == 0) g_fastA = ok;
}

// ---------------- LN over C=256 + chunk split ----------------
__global__ void k_ln_split(const float* __restrict__ x,
                           const float* __restrict__ w,
                           const float* __restrict__ bb) {
    int bid = blockIdx.x;
    int b   = bid >> 7;
    int l0  = (bid & 127) << 5;
    __shared__ float t[256*33];
    __shared__ float s_sum[8][32], s_sq[8][32];
    __shared__ float s_mean[32], s_rstd[32];
    int tid = threadIdx.x;
    const float* xb = x + (size_t)b * 256 * LQ;
    for (int idx = tid; idx < 256*32; idx += 256) {
        int c = idx >> 5, j = idx & 31;
        t[c*33 + j] = xb[(size_t)c*LQ + l0 + j];
    }
    __syncthreads();
    int j = tid & 31, g = tid >> 5;
    float sum = 0.f, sq = 0.f;
    for (int c = g*32; c < g*32 + 32; ++c) {
        float v = t[c*33 + j];
        sum += v; sq += v*v;
    }
    s_sum[g][j] = sum; s_sq[g][j] = sq;
    __syncthreads();
    if (g == 0) {
        float S = 0.f, Q = 0.f;
        #pragma unroll
        for (int gg = 0; gg < 8; ++gg) { S += s_sum[gg][j]; Q += s_sq[gg][j]; }
        float m = S * (1.f/256.f);
        float v = Q * (1.f/256.f) - m*m;
        s_mean[j] = m; s_rstd[j] = rsqrtf(v + 1e-5f);
    }
    __syncthreads();
    for (int idx = tid; idx < 2048; idx += 256) {
        int chunk = idx >> 9;
        int l = (idx >> 4) & 31;
        int d4 = idx & 15;
        int c0 = chunk*64 + d4*4;
        float mn = s_mean[l], rs = s_rstd[l];
        float4 wv = *reinterpret_cast<const float4*>(&w[c0]);
        float4 bv = *reinterpret_cast<const float4*>(&bb[c0]);
        float4 o;
        o.x = (t[(c0+0)*33 + l] - mn)*rs*wv.x + bv.x;
        o.y = (t[(c0+1)*33 + l] - mn)*rs*wv.y + bv.y;
        o.z = (t[(c0+2)*33 + l] - mn)*rs*wv.z + bv.z;
        o.w = (t[(c0+3)*33 + l] - mn)*rs*wv.w + bv.w;
        *reinterpret_cast<float4*>(
            &g_xi[(((size_t)(chunk*8 + b))*LQ + l0 + l)*64 + d4*4]) = o;
    }
}

// ---------------- mma helpers ----------------
__device__ __forceinline__ void mma8(float c[4], const uint32_t a[4], const uint32_t b[2]) {
    asm volatile(
        "mma.sync.aligned.m16n8k8.row.col.f32.tf32.tf32.f32 "
        "{%0,%1,%2,%3}, {%4,%5,%6,%7}, {%8,%9}, {%0,%1,%2,%3};\n"
        : "+f"(c[0]), "+f"(c[1]), "+f"(c[2]), "+f"(c[3])
        : "r"(a[0]), "r"(a[1]), "r"(a[2]), "r"(a[3]), "r"(b[0]), "r"(b[1]));
}

__device__ __forceinline__ void cp16(uint32_t saddr, const void* gptr, bool valid) {
    int sz = valid ? 16 : 0;
    asm volatile("cp.async.cg.shared.global [%0], [%1], 16, %2;\n"
                 :: "r"(saddr), "l"(gptr), "r"(sz));
}
#define CP_COMMIT() asm volatile("cp.async.commit_group;\n" ::: "memory")
#define CP_WAIT1()  asm volatile("cp.async.wait_group 1;\n" ::: "memory")

__device__ __forceinline__ float gelu_exact(float v) {
    return 0.5f * v * (1.f + erff(v * 0.70710678118654752f));
}

// OP: 1 in_proj  5 x_proj+dt  0 out_proj+LN64  4 conv1x1+BNstats
// BIG ops (1,4,5): 128x128 tile, warp tile 64x32. OP0: 128x64, warp 32x32.
template<int OP>
__global__ void __launch_bounds__(256, ((OP==1||OP==4||OP==5) ? 2 : 3))
k_gemm(const float* __restrict__ W,
       const float* __restrict__ bias,
       const float* __restrict__ aux) {
    constexpr int N  = (OP==1||OP==4) ? 256 : (OP==5 ? 160 : 64);
    constexpr int K  = (OP==1) ? 64 : ((OP==4) ? 256 : 128);
    constexpr bool BIG = (OP==1||OP==4||OP==5);
    constexpr int BM = 128;
    constexpr int BN = BIG ? 128 : 64;
    constexpr int WM = BIG ? 2 : 4;
    constexpr int TM = BIG ? 4 : 2;
    constexpr int PK = 20;
    constexpr int NTILES = K / 16;
    constexpr bool GUARD = (N % BN) != 0;
    constexpr int ASZ = BM * PK;

    __shared__ __align__(16) float sm[3][(BM + BN) * PK];
    __shared__ float sred[768];

    const float* Asrc = (OP==1) ? g_xi : (OP==5) ? g_u : (OP==0) ? g_y : g_inter;
    const float* Bsrc = (OP==4) ? g_wp : (OP==5) ? g_w2 : W;

    int tid = threadIdx.x;
    int lane = tid & 31, w = tid >> 5;
    int wm = w % WM, wn = w / WM;
    uint32_t m0 = blockIdx.y * BM, n0 = blockIdx.x * BN;
    int mbase = wm*(TM*16), nbase = wn*32;
    int r = lane >> 2, t4 = lane & 3;

    float acc[TM][4][4] = {};

    int lm = tid >> 2, lkq = tid & 3;

    auto issue_tile = [&](int t) {
        if (t < NTILES) {
            uint32_t k0 = t*16;
            int buf = t % 3;
            uint32_t sA = (uint32_t)__cvta_generic_to_shared(&sm[buf][0]);
            uint32_t sB = sA + ASZ*4;
            #pragma unroll
            for (int i = 0; i < BM/64; ++i) {
                uint32_t m = lm + i*64;
                cp16(sA + (m*PK + lkq*4)*4,
                     &Asrc[(m0 + m)*K + k0 + lkq*4], true);
            }
            #pragma unroll
            for (int i = 0; i < BN/64; ++i) {
                uint32_t n = lm + i*64;
                bool ok = !GUARD || (n0 + n) < N;
                cp16(sB + (n*PK + lkq*4)*4,
                     &Bsrc[(n0 + n)*K + k0 + lkq*4], ok);
            }
        }
        CP_COMMIT();
    };
    auto compute = [&](int buf) {
        const uint32_t* A32 = reinterpret_cast<const uint32_t*>(&sm[buf][0]);
        const uint32_t* B32 = A32 + ASZ;
        #pragma unroll
        for (int g = 0; g < 2; ++g) {
            int kb = g*8 + t4;
            uint32_t af[TM][4], bf[4][2];
            #pragma unroll
            for (int tm = 0; tm < TM; ++tm) {
                int row = mbase + tm*16 + r;
                af[tm][0] = A32[row*PK + kb];
                af[tm][1] = A32[(row+8)*PK + kb];
                af[tm][2] = A32[row*PK + kb + 4];
                af[tm][3] = A32[(row+8)*PK + kb + 4];
            }
            #pragma unroll
            for (int tn = 0; tn < 4; ++tn) {
                int col = nbase + tn*8 + r;
                bf[tn][0] = B32[col*PK + kb];
                bf[tn][1] = B32[col*PK + kb + 4];
            }
            #pragma unroll
            for (int tm = 0; tm < TM; ++tm)
                #pragma unroll
                for (int tn = 0; tn < 4; ++tn)
                    mma8(acc[tm][tn], af[tm], bf[tn]);
        }
    };

    issue_tile(0);
    issue_tile(1);
    #pragma unroll 1
    for (int t = 0; t < NTILES; ++t) {
        CP_WAIT1();
        __syncthreads();
        issue_tile(t + 2);
        compute(t % 3);
    }

    // ---- epilogue ----
    if constexpr (OP == 0) {
        float* rs_ = sred;
        float* rq_ = sred + 256;
        float* s_mean = sred + 512;
        float* s_rstd = sred + 640;
        float ps[4], pq[4];
        #pragma unroll
        for (int tm = 0; tm < 2; ++tm)
            #pragma unroll
            for (int h = 0; h < 2; ++h) {
                float s = 0.f, q = 0.f;
                #pragma unroll
                for (int tn = 0; tn < 4; ++tn)
                    #pragma unroll
                    for (int e = 0; e < 2; ++e) {
                        float v = acc[tm][tn][h*2 + e];
                        s += v; q += v*v;
                    }
                ps[tm*2 + h] = s; pq[tm*2 + h] = q;
            }
        #pragma unroll
        for (int o = 1; o < 4; o <<= 1) {
            #pragma unroll
            for (int i = 0; i < 4; ++i) {
                ps[i] += __shfl_xor_sync(0xffffffff, ps[i], o);
                pq[i] += __shfl_xor_sync(0xffffffff, pq[i], o);
            }
        }
        if (t4 == 0) {
            #pragma unroll
            for (int tm = 0; tm < 2; ++tm)
                #pragma unroll
                for (int h = 0; h < 2; ++h) {
                    int row = mbase + tm*16 + r + h*8;
                    rs_[wn*128 + row] = ps[tm*2 + h];
                    rq_[wn*128 + row] = pq[tm*2 + h];
                }
        }
        __syncthreads();
        if (tid < 128) {
            float S = rs_[tid] + rs_[128 + tid];
            float Q = rq_[tid] + rq_[128 + tid];
            float mn = S * (1.f/64.f);
            float var = Q * (1.f/64.f) - mn*mn;
            s_mean[tid] = mn; s_rstd[tid] = rsqrtf(var + 1e-5f);
        }
        __syncthreads();
        #pragma unroll
        for (int tm = 0; tm < 2; ++tm)
            #pragma unroll
            for (int tn = 0; tn < 4; ++tn)
                #pragma unroll
                for (int h = 0; h < 2; ++h) {
                    int row = mbase + tm*16 + r + h*8;
                    uint32_t m = m0 + row;
                    int n = nbase + tn*8 + t4*2;
                    float2 o;
                    o.x = (acc[tm][tn][h*2+0] - s_mean[row]) * s_rstd[row]
                          * bias[n]   + aux[n];
                    o.y = (acc[tm][tn][h*2+1] - s_mean[row]) * s_rstd[row]
                          * bias[n+1] + aux[n+1];
                    *reinterpret_cast<float2*>(&g_lnb[m*64u + n]) = o;
                }
    } else {
        float cs[4][2], cq[4][2];
        if constexpr (OP == 4) {
            #pragma unroll
            for (int tn = 0; tn < 4; ++tn) {
                cs[tn][0] = cs[tn][1] = 0.f;
                cq[tn][0] = cq[tn][1] = 0.f;
            }
        }
        #pragma unroll
        for (int tm = 0; tm < TM; ++tm) {
            #pragma unroll
            for (int tn = 0; tn < 4; ++tn) {
                #pragma unroll
                for (int h = 0; h < 2; ++h) {
                    uint32_t m = m0 + mbase + tm*16 + r + h*8;
                    uint32_t n = n0 + nbase + tn*8 + t4*2;
                    if (GUARD && n >= N) continue;
                    float v0 = acc[tm][tn][h*2+0];
                    float v1 = acc[tm][tn][h*2+1];
                    if (OP == 1) {
                        float2 o = make_float2(v0, v1);
                        if (n < 128)
                            *reinterpret_cast<float2*>(&g_xc[m*128u + n]) = o;
                        else
                            *reinterpret_cast<float2*>(&g_z[m*128u + n - 128]) = o;
                    } else if (OP == 5) {
                        if (n < 32) {
                            *reinterpret_cast<float2*>(&g_bc[m*32u + n]) =
                                make_float2(v0, v1);
                        } else {
                            int col = n - 32;
                            float a0 = v0 + bias[col];
                            float a1 = v1 + bias[col+1];
                            float2 o;
                            o.x = (a0 > 20.f) ? a0 : log1pf(expf(a0));
                            o.y = (a1 > 20.f) ? a1 : log1pf(expf(a1));
                            *reinterpret_cast<float2*>(&g_dt[m*128u + col]) = o;
                        }
                    } else { // OP == 4
                        float2 o = make_float2(v0 + bias[n], v1 + bias[n+1]);
                        *reinterpret_cast<float2*>(&g_cv[m*256u + n]) = o;
                        cs[tn][0] += o.x; cq[tn][0] += o.x*o.x;
                        cs[tn][1] += o.y; cq[tn][1] += o.y*o.y;
                    }
                }
            }
        }
        if constexpr (OP == 4) {
            #pragma unroll
            for (int tn = 0; tn < 4; ++tn)
                #pragma unroll
                for (int e = 0; e < 2; ++e) {
                    float s = cs[tn][e], q = cq[tn][e];
                    #pragma unroll
                    for (int o = 4; o <= 16; o <<= 1) {
                        s += __shfl_xor_sync(0xffffffff, s, o);
                        q += __shfl_xor_sync(0xffffffff, q, o);
                    }
                    if (r == 0) {
                        int col = nbase + tn*8 + t4*2 + e;
                        sred[wm*128 + col] = s;
                        sred[256 + wm*128 + col] = q;
                    }
                }
            __syncthreads();
            if (tid < 128) {
                uint32_t gcol = n0 + tid;
                g_ps[blockIdx.y*256u + gcol] = sred[tid] + sred[128 + tid];
                g_pq[blockIdx.y*256u + gcol] = sred[256 + tid] + sred[384 + tid];
            }
        }
    }
}

// ---------------- fused MLP v2 ----------------
__global__ void __launch_bounds__(256, 2)
k_mlp2(const float* __restrict__ w1, const float* __restrict__ b1,
       const float* __restrict__ w2, const float* __restrict__ b2,
       const float* __restrict__ skp) {
    extern __shared__ float dsm[];
    constexpr int PIPE = (64 + 128) * 20;
    float* Pb = dsm;
    float* Hs = dsm + 2*PIPE;

    int tid = threadIdx.x;
    int lane = tid & 31, w = tid >> 5;
    int r = lane >> 2, t4 = lane & 3;
    int wm = w & 1, wn = w >> 1;
    int lm = tid >> 2, lkq = tid & 3;
    float sk = skp[0];
    uint32_t m0 = blockIdx.y * 64;
    const uint32_t* Hu = reinterpret_cast<const uint32_t*>(Hs);

    #pragma unroll 1
    for (int nb = 0; nb < 2; ++nb) {
        float acc[2][4][4] = {};
        auto issue1 = [&](int t) {
            if (t < 4) {
                uint32_t sA = (uint32_t)__cvta_generic_to_shared(&Pb[(t & 1)*PIPE]);
                uint32_t sB = sA + 64*20*4;
                cp16(sA + (lm*20 + lkq*4)*4,
                     &g_lnb[(m0 + lm)*64u + t*16 + lkq*4], true);
                #pragma unroll
                for (int i = 0; i < 2; ++i) {
                    int n = lm + i*64;
                    cp16(sB + (n*20 + lkq*4)*4,
                         &w1[(nb*128 + n)*64u + t*16 + lkq*4], true);
                }
            }
            CP_COMMIT();
        };
        issue1(0);
        #pragma unroll 1
        for (int t = 0; t < 4; ++t) {
            issue1(t + 1);
            CP_WAIT1();
            __syncthreads();
            const uint32_t* A32 = reinterpret_cast<const uint32_t*>(&Pb[(t & 1)*PIPE]);
            const uint32_t* B32 = A32 + 64*20;
            #pragma unroll
            for (int g = 0; g < 2; ++g) {
                int kb = g*8 + t4;
                uint32_t af[2][4], bf[4][2];
                #pragma unroll
                for (int tm = 0; tm < 2; ++tm) {
                    int row = wm*32 + tm*16 + r;
                    af[tm][0] = A32[row*20 + kb];
                    af[tm][1] = A32[(row+8)*20 + kb];
                    af[tm][2] = A32[row*20 + kb + 4];
                    af[tm][3] = A32[(row+8)*20 + kb + 4];
                }
                #pragma unroll
                for (int tn = 0; tn < 4; ++tn) {
                    int col = wn*32 + tn*8 + r;
                    bf[tn][0] = B32[col*20 + kb];
                    bf[tn][1] = B32[col*20 + kb + 4];
                }
                #pragma unroll
                for (int tm = 0; tm < 2; ++tm)
                    #pragma unroll
                    for (int tn = 0; tn < 4; ++tn)
                        mma8(acc[tm][tn], af[tm], bf[tn]);
            }
            __syncthreads();
        }
        #pragma unroll
        for (int tm = 0; tm < 2; ++tm)
            #pragma unroll
            for (int tn = 0; tn < 4; ++tn)
                #pragma unroll
                for (int h = 0; h < 2; ++h) {
                    int row = wm*32 + tm*16 + r + h*8;
                    int col = nb*128 + wn*32 + tn*8 + t4*2;
                    float2 o;
                    o.x = gelu_exact(acc[tm][tn][h*2+0] + b1[col]);
                    o.y = gelu_exact(acc[tm][tn][h*2+1] + b1[col+1]);
                    *reinterpret_cast<float2*>(&Hs[row*260 + col]) = o;
                }
    }
    __syncthreads();

    float acc2[2][2][4] = {};
    auto issue2 = [&](int t) {
        if (t < 16) {
            uint32_t sB = (uint32_t)__cvta_generic_to_shared(&Pb[(t & 1)*PIPE]);
            cp16(sB + (lm*20 + lkq*4)*4,
                 &w2[lm*256u + t*16 + lkq*4], true);
        }
        CP_COMMIT();
    };
    issue2(0);
    #pragma unroll 1
    for (int t = 0; t < 16; ++t) {
        issue2(t + 1);
        CP_WAIT1();
        __syncthreads();
        const uint32_t* B32 = reinterpret_cast<const uint32_t*>(&Pb[(t & 1)*PIPE]);
        #pragma unroll
        for (int g = 0; g < 2; ++g) {
            int kb = g*8 + t4;
            int kg = t*16 + kb;
            uint32_t af[2][4], bf[2][2];
            #pragma unroll
            for (int tm = 0; tm < 2; ++tm) {
                int row = wm*32 + tm*16 + r;
                af[tm][0] = Hu[row*260 + kg];
                af[tm][1] = Hu[(row+8)*260 + kg];
                af[tm][2] = Hu[row*260 + kg + 4];
                af[tm][3] = Hu[(row+8)*260 + kg + 4];
            }
            #pragma unroll
            for (int tn = 0; tn < 2; ++tn) {
                int col = wn*16 + tn*8 + r;
                bf[tn][0] = B32[col*20 + kb];
                bf[tn][1] = B32[col*20 + kb + 4];
            }
            #pragma unroll
            for (int tm = 0; tm < 2; ++tm)
                #pragma unroll
                for (int tn = 0; tn < 2; ++tn)
                    mma8(acc2[tm][tn], af[tm], bf[tn]);
        }
        __syncthreads();
    }
    #pragma unroll
    for (int tm = 0; tm < 2; ++tm)
        #pragma unroll
        for (int tn = 0; tn < 2; ++tn)
            #pragma unroll
            for (int h = 0; h < 2; ++h) {
                int row = wm*32 + tm*16 + r + h*8;
                int col = wn*16 + tn*8 + t4*2;
                uint32_t m = m0 + row;
                float2 o;
                o.x = acc2[tm][tn][h*2+0] + b2[col]   + sk * g_xi[m*64u + col];
                o.y = acc2[tm][tn][h*2+1] + b2[col+1] + sk * g_xi[m*64u + col + 1];
                uint32_t l = m & (LQ-1);
                uint32_t nb2 = m >> 12;
                uint32_t chunk = nb2 >> 3, b = nb2 & 7;
                *reinterpret_cast<float2*>(
                    &g_inter[((b*LQ + l)*256u) + chunk*64 + col]) = o;
            }
}

// ---------------- depthwise causal conv1d(4) + bias + silu ----------------
__global__ void k_conv_silu(const float* __restrict__ cw,
                            const float* __restrict__ cb) {
    size_t id = (size_t)blockIdx.x * 256 + threadIdx.x;
    int d = id & 127;
    size_t q = id >> 7;
    int lg = (int)(q & 1023);
    size_t n = q >> 10;
    int l0 = lg * 4;
    const float* base = g_xc + ((n*LQ) << 7) + d;
    float w0 = cw[d*4], w1 = cw[d*4+1], w2 = cw[d*4+2], w3 = cw[d*4+3];
    float b = cb[d];
    float xv[7];
    #pragma unroll
    for (int t = 0; t < 7; ++t) {
        int ll = l0 - 3 + t;
        xv[t] = (ll >= 0) ? base[(size_t)ll*128] : 0.f;
    }
    float* outp = g_u + ((n*LQ) << 7) + ((size_t)l0 << 7) + d;
    #pragma unroll
    for (int i = 0; i < 4; ++i) {
        float acc = b;
        acc = fmaf(xv[i],   w0, acc);
        acc = fmaf(xv[i+1], w1, acc);
        acc = fmaf(xv[i+2], w2, acc);
        acc = fmaf(xv[i+3], w3, acc);
        float sig = 1.f / (1.f + __expf(-acc));
        outp[(size_t)i*128] = acc * sig;
    }
}

// ---------------- scan phase 1 ----------------
__global__ void k_scan1() {
    int blk = blockIdx.x;
    int n = blk >> 5;
    int g = blk & 31;
    int d = threadIdx.x;
    int fast = g_fastA;
    float A0 = g_Aa[d*DS];
    float A[DS], h[DS];
    #pragma unroll
    for (int s = 0; s < DS; ++s) { A[s] = g_Aa[d*DS + s]; h[s] = 0.f; }
    float dtsum = 0.f;
    __shared__ __align__(16) float sBC[16*32];
    size_t l0 = (size_t)g * CLEN;
    size_t base = ((size_t)n * LQ) * 128;
    for (int t0 = 0; t0 < CLEN; t0 += 16) {
        reinterpret_cast<float4*>(sBC)[d] =
            reinterpret_cast<const float4*>(g_bc + ((size_t)n*LQ + l0 + t0)*32)[d];
        __syncthreads();
        for (int st = 0; st < 16; ++st) {
            size_t l = l0 + t0 + st;
            float dt = g_dt[base + l*128 + d];
            float uu = g_u [base + l*128 + d];
            float du = dt * uu;
            dtsum += dt;
            const float* Bl = &sBC[st*32];
            if (fast) {
                float p = __expf(dt * A0);
                float a = 1.f;
                #pragma unroll
                for (int s = 0; s < DS; ++s) {
                    a *= p;
                    h[s] = fmaf(a, h[s], du * Bl[s]);
                }
            } else {
                #pragma unroll
                for (int s = 0; s < DS; ++s) {
                    float a = __expf(dt * A[s]);
                    h[s] = fmaf(a, h[s], du * Bl[s]);
                }
            }
        }
        __syncthreads();
    }
    size_t off = (((size_t)(n*NCH + g))*128 + d)*DS;
    if (fast) {
        float p = __expf(dtsum * A0);
        float a = 1.f;
        #pragma unroll
        for (int s = 0; s < DS; ++s) { a *= p; g_P[off + s] = a; g_hend[off + s] = h[s]; }
    } else {
        #pragma unroll
        for (int s = 0; s < DS; ++s) {
            g_P[off + s] = __expf(A[s] * dtsum);
            g_hend[off + s] = h[s];
        }
    }
}

// ---------------- scan phase 2 ----------------
__global__ void k_scan2() {
    int lane = blockIdx.x * 256 + threadIdx.x;
    int s = lane & 15;
    int d = (lane >> 4) & 127;
    int n = lane >> 11;
    float h = 0.f;
    for (int g = 0; g < NCH; ++g) {
        size_t off = (((size_t)(n*NCH + g))*128 + d)*DS + s;
        g_hin[off] = h;
        h = g_P[off]*h + g_hend[off];
    }
}

// ---------------- scan phase 3 ----------------
__global__ void k_scan3(const float* __restrict__ Dp) {
    int blk = blockIdx.x;
    int n = blk >> 5;
    int g = blk & 31;
    int d = threadIdx.x;
    int fast = g_fastA;
    float A0 = g_Aa[d*DS];
    float A[DS], h[DS];
    size_t off = (((size_t)(n*NCH + g))*128 + d)*DS;
    #pragma unroll
    for (int s = 0; s < DS; ++s) { A[s] = g_Aa[d*DS + s]; h[s] = g_hin[off + s]; }
    float Dd = Dp[d];
    __shared__ __align__(16) float sBC[16*32];
    size_t l0 = (size_t)g * CLEN;
    size_t base = ((size_t)n * LQ) * 128;
    for (int t0 = 0; t0 < CLEN; t0 += 16) {
        reinterpret_cast<float4*>(sBC)[d] =
            reinterpret_cast<const float4*>(g_bc + ((size_t)n*LQ + l0 + t0)*32)[d];
        __syncthreads();
        for (int st = 0; st < 16; ++st) {
            size_t l = l0 + t0 + st;
            float dt = g_dt[base + l*128 + d];
            float uu = g_u [base + l*128 + d];
            float zz = g_z [base + l*128 + d];
            float du = dt * uu;
            const float* Bl = &sBC[st*32];
            const float* Cl = Bl + 16;
            float y = 0.f;
            if (fast) {
                float p = __expf(dt * A0);
                float a = 1.f;
                #pragma unroll
                for (int s = 0; s < DS; ++s) {
                    a *= p;
                    h[s] = fmaf(a, h[s], du * Bl[s]);
                    y = fmaf(h[s], Cl[s], y);
                }
            } else {
                #pragma unroll
                for (int s = 0; s < DS; ++s) {
                    float a = __expf(dt * A[s]);
                    h[s] = fmaf(a, h[s], du * Bl[s]);
                    y = fmaf(h[s], Cl[s], y);
                }
            }
            y += uu * Dd;
            float sz = zz / (1.f + __expf(-zz));
            g_y[base + l*128 + d] = y * sz;
        }
        __syncthreads();
    }
}

// ---------------- BN finalize ----------------
__global__ void k_bnfin(const float* __restrict__ gamma,
                        const float* __restrict__ beta) {
    int o = threadIdx.x;
    float s = 0.f, q = 0.f;
    for (int k = 0; k < 256; ++k) { s += g_ps[k*256 + o]; q += g_pq[k*256 + o]; }
    float mean = s * (1.f/32768.f);
    float var  = q * (1.f/32768.f) - mean*mean;
    float rg = rsqrtf(var + 1e-5f) * gamma[o];
    g_bnA[o] = rg;
    g_bnB[o] = beta[o] - mean*rg;
}

// ---------------- transpose + BN + relu ----------------
__global__ void k_out(float* __restrict__ out) {
    int bid = blockIdx.x;
    int lg = bid & 127;
    int og = (bid >> 7) & 7;
    int b  = bid >> 10;
    __shared__ float tile[32][33];
    int tid = threadIdx.x;
    int o_in = tid & 31;
    int l_in = tid >> 5;
    size_t l0 = (size_t)lg * 32, o0 = (size_t)og * 32;
    float a = g_bnA[o0 + o_in], c = g_bnB[o0 + o_in];
    #pragma unroll
    for (int i = 0; i < 4; ++i) {
        int l = l_in + i*8;
        float v = g_cv[((size_t)b*LQ + l0 + l)*256 + o0 + o_in];
        tile[l][o_in] = v*a + c;
    }
    __syncthreads();
    int l_out = tid & 31;
    int o_off = tid >> 5;
    #pragma unroll
    for (int i = 0; i < 4; ++i) {
        int o = o_off + i*8;
        out[((size_t)(b*256 + o0 + o))*LQ + l0 + l_out] = fmaxf(tile[l_out][o], 0.f);
    }
}

// ---------------- launcher ----------------
extern "C" void kernel_launch(void* const* d_in, const int* in_sizes, int n_in,
                              void* d_out, int out_size) {
    const float* x         = (const float*)d_in[0];
    const float* norm_w    = (const float*)d_in[1];
    const float* norm_b    = (const float*)d_in[2];
    const float* norm1_w   = (const float*)d_in[3];
    const float* norm1_b   = (const float*)d_in[4];
    const float* in_proj_w = (const float*)d_in[5];
    const float* conv_w    = (const float*)d_in[6];
    const float* conv_b    = (const float*)d_in[7];
    const float* x_proj_w  = (const float*)d_in[8];
    const float* dt_w      = (const float*)d_in[9];
    const float* dt_b      = (const float*)d_in[10];
    const float* A_log     = (const float*)d_in[11];
    const float* D_param   = (const float*)d_in[12];
    const float* out_proj_w= (const float*)d_in[13];
    const float* fc1_w     = (const float*)d_in[14];
    const float* fc1_b     = (const float*)d_in[15];
    const float* fc2_w     = (const float*)d_in[16];
    const float* fc2_b     = (const float*)d_in[17];
    const float* skip      = (const float*)d_in[18];
    const float* oc_w      = (const float*)d_in[19];
    const float* oc_b      = (const float*)d_in[20];
    const float* gamma     = (const float*)d_in[21];
    const float* beta      = (const float*)d_in[22];
    float* out = (float*)d_out;

    const int MLP_SMEM = (2*(64+128)*20 + 64*260) * 4;
    cudaFuncSetAttribute(k_mlp2, cudaFuncAttributeMaxDynamicSharedMemorySize, MLP_SMEM);

    k_prep<<<256, 256>>>(A_log, oc_w);
    k_prep2<<<80, 256>>>(x_proj_w, dt_w);
    k_checkA<<<1, 256>>>();
    k_ln_split<<<1024, 256>>>(x, norm_w, norm_b);
    k_gemm<1><<<dim3(2, M1/128), 256>>>(in_proj_w,  nullptr, nullptr);
    k_conv_silu<<<16384, 256>>>(conv_w, conv_b);
    k_gemm<5><<<dim3(2, M1/128), 256>>>(nullptr,    dt_b, nullptr);
    k_scan1<<<NBAT*NCH, 128>>>();
    k_scan2<<<256, 256>>>();
    k_scan3<<<NBAT*NCH, 128>>>(D_param);
    k_gemm<0><<<dim3(1, M1/128), 256>>>(out_proj_w, norm1_w, norm1_b);
    k_mlp2<<<dim3(1, M1/64), 256, MLP_SMEM>>>(fc1_w, fc1_b, fc2_w, fc2_b, skip);
    k_gemm<4><<<dim3(2, M2/128), 256>>>(nullptr,    oc_b, nullptr);
    k_bnfin<<<1, 256>>>(gamma, beta);
    k_out<<<8192, 256>>>(out);
}

// round 16
// speedup vs baseline: 1.0642x; 1.0642x over previous
#include <cuda_runtime.h>
#include <math.h>
#include <stdint.h>

// ---------------- problem constants ----------------
#define LQ   4096
#define NBAT 32
#define M1   (NBAT*LQ)
#define DI   128
#define DS   16
#define NCH  32
#define CLEN (LQ/NCH)
#define M2   (8*LQ)

// ---------------- scratch ----------------
__device__ float g_xi  [(size_t)M1*64];
__device__ float g_xc  [(size_t)M1*DI];
__device__ float g_z   [(size_t)M1*DI];
__device__ float g_u   [(size_t)M1*DI];
__device__ float g_dt  [(size_t)M1*DI];
__device__ __align__(16) float g_bc [(size_t)M1*32];
__device__ float g_y   [(size_t)M1*DI];
__device__ float g_lnb [(size_t)M1*64];
__device__ float g_inter[(size_t)M2*256];
__device__ float g_cv  [(size_t)M2*256];
__device__ float g_P   [NBAT*NCH*DI*DS];
__device__ float g_hend[NBAT*NCH*DI*DS];
__device__ float g_hin [NBAT*NCH*DI*DS];
__device__ float g_Aa  [DI*DS];
__device__ float g_wp  [256*256];
__device__ float g_w2  [160*128];
__device__ float g_ps  [512*256];
__device__ float g_pq  [512*256];
__device__ float g_bnA [256];
__device__ float g_bnB [256];
__device__ int   g_fastA;

// ---------------- prep (A, conv-w permute, extended x_proj weight) -------
__global__ void k_prep(const float* __restrict__ A_log,
                       const float* __restrict__ oc_w,
                       const float* __restrict__ xw,
                       const float* __restrict__ dtw) {
    int i = blockIdx.x * blockDim.x + threadIdx.x;
    if (i < DI*DS) g_Aa[i] = -expf(A_log[i]);
    if (i < 256*256) {
        int o = i >> 8, c = i & 255;
        int dm = c >> 2, ch = c & 3;
        g_wp[o*256 + ch*64 + dm] = oc_w[i];
    }
    if (i < 160*128) {
        int row = i >> 7, k = i & 127;
        if (row < 32) {
            g_w2[i] = xw[(4 + row)*128 + k];
        } else {
            int d = row - 32;
            float s = 0.f;
            #pragma unroll
            for (int r = 0; r < 4; ++r) s = fmaf(dtw[d*4 + r], xw[r*128 + k], s);
            g_w2[i] = s;
        }
    }
}

__global__ void k_checkA() {
    __shared__ int ok;
    if (threadIdx.x == 0) ok = 1;
    __syncthreads();
    for (int i = threadIdx.x; i < DI*DS; i += 256) {
        int d = i >> 4, s = i & 15;
        float a0  = g_Aa[d*16];
        float ref = (float)(s + 1) * a0;
        if (fabsf(g_Aa[i] - ref) > 1e-4f * fabsf(ref) + 1e-6f) atomicAnd(&ok, 0);
    }
    __syncthreads();
    if (threadIdx.x == 0) g_fastA = ok;
}

// ---------------- LN over C=256 + chunk split ----------------
__global__ void k_ln_split(const float* __restrict__ x,
                           const float* __restrict__ w,
                           const float* __restrict__ bb) {
    int bid = blockIdx.x;
    int b   = bid >> 7;
    int l0  = (bid & 127) << 5;
    __shared__ float t[256*33];
    __shared__ float s_sum[8][32], s_sq[8][32];
    __shared__ float s_mean[32], s_rstd[32];
    int tid = threadIdx.x;
    const float* xb = x + (size_t)b * 256 * LQ;
    for (int idx = tid; idx < 256*32; idx += 256) {
        int c = idx >> 5, j = idx & 31;
        t[c*33 + j] = xb[(size_t)c*LQ + l0 + j];
    }
    __syncthreads();
    int j = tid & 31, g = tid >> 5;
    float sum = 0.f, sq = 0.f;
    for (int c = g*32; c < g*32 + 32; ++c) {
        float v = t[c*33 + j];
        sum += v; sq += v*v;
    }
    s_sum[g][j] = sum; s_sq[g][j] = sq;
    __syncthreads();
    if (g == 0) {
        float S = 0.f, Q = 0.f;
        #pragma unroll
        for (int gg = 0; gg < 8; ++gg) { S += s_sum[gg][j]; Q += s_sq[gg][j]; }
        float m = S * (1.f/256.f);
        float v = Q * (1.f/256.f) - m*m;
        s_mean[j] = m; s_rstd[j] = rsqrtf(v + 1e-5f);
    }
    __syncthreads();
    for (int idx = tid; idx < 2048; idx += 256) {
        int chunk = idx >> 9;
        int l = (idx >> 4) & 31;
        int d4 = idx & 15;
        int c0 = chunk*64 + d4*4;
        float mn = s_mean[l], rs = s_rstd[l];
        float4 wv = *reinterpret_cast<const float4*>(&w[c0]);
        float4 bv = *reinterpret_cast<const float4*>(&bb[c0]);
        float4 o;
        o.x = (t[(c0+0)*33 + l] - mn)*rs*wv.x + bv.x;
        o.y = (t[(c0+1)*33 + l] - mn)*rs*wv.y + bv.y;
        o.z = (t[(c0+2)*33 + l] - mn)*rs*wv.z + bv.z;
        o.w = (t[(c0+3)*33 + l] - mn)*rs*wv.w + bv.w;
        *reinterpret_cast<float4*>(
            &g_xi[(((size_t)(chunk*8 + b))*LQ + l0 + l)*64 + d4*4]) = o;
    }
}

// ---------------- mma helpers ----------------
__device__ __forceinline__ void mma8(float c[4], const uint32_t a[4], const uint32_t b[2]) {
    asm volatile(
        "mma.sync.aligned.m16n8k8.row.col.f32.tf32.tf32.f32 "
        "{%0,%1,%2,%3}, {%4,%5,%6,%7}, {%8,%9}, {%0,%1,%2,%3};\n"
        : "+f"(c[0]), "+f"(c[1]), "+f"(c[2]), "+f"(c[3])
        : "r"(a[0]), "r"(a[1]), "r"(a[2]), "r"(a[3]), "r"(b[0]), "r"(b[1]));
}

__device__ __forceinline__ void cp16(uint32_t saddr, const void* gptr, bool valid) {
    int sz = valid ? 16 : 0;
    asm volatile("cp.async.cg.shared.global [%0], [%1], 16, %2;\n"
                 :: "r"(saddr), "l"(gptr), "r"(sz));
}
#define CP_COMMIT() asm volatile("cp.async.commit_group;\n" ::: "memory")
#define CP_WAIT1()  asm volatile("cp.async.wait_group 1;\n" ::: "memory")

__device__ __forceinline__ float gelu_exact(float v) {
    return 0.5f * v * (1.f + erff(v * 0.70710678118654752f));
}

// OP: 1 in_proj  5 x_proj+dt  0 out_proj+LN64  4 conv1x1+BNstats
// BIG ops (1,4): 128x128 tile, warp tile 64x32. Others: 128x64, warp 32x32.
template<int OP>
__global__ void __launch_bounds__(256, ((OP==1||OP==4) ? 2 : 3))
k_gemm(const float* __restrict__ W,
       const float* __restrict__ bias,
       const float* __restrict__ aux) {
    constexpr int N  = (OP==1||OP==4) ? 256 : (OP==5 ? 160 : 64);
    constexpr int K  = (OP==1) ? 64 : ((OP==4) ? 256 : 128);
    constexpr bool BIG = (OP==1||OP==4);
    constexpr int BM = 128;
    constexpr int BN = BIG ? 128 : 64;
    constexpr int WM = BIG ? 2 : 4;
    constexpr int TM = BIG ? 4 : 2;
    constexpr int PK = 20;
    constexpr int NTILES = K / 16;
    constexpr bool GUARD = (N % BN) != 0;
    constexpr int ASZ = BM * PK;

    __shared__ __align__(16) float sm[3][(BM + BN) * PK];
    __shared__ float sred[768];

    const float* Asrc = (OP==1) ? g_xi : (OP==5) ? g_u : (OP==0) ? g_y : g_inter;
    const float* Bsrc = (OP==4) ? g_wp : (OP==5) ? g_w2 : W;

    int tid = threadIdx.x;
    int lane = tid & 31, w = tid >> 5;
    int wm = w % WM, wn = w / WM;
    uint32_t m0 = blockIdx.y * BM, n0 = blockIdx.x * BN;
    int mbase = wm*(TM*16), nbase = wn*32;
    int r = lane >> 2, t4 = lane & 3;

    float acc[TM][4][4] = {};

    int lm = tid >> 2, lkq = tid & 3;

    auto issue_tile = [&](int t) {
        if (t < NTILES) {
            uint32_t k0 = t*16;
            int buf = t % 3;
            uint32_t sA = (uint32_t)__cvta_generic_to_shared(&sm[buf][0]);
            uint32_t sB = sA + ASZ*4;
            #pragma unroll
            for (int i = 0; i < BM/64; ++i) {
                uint32_t m = lm + i*64;
                cp16(sA + (m*PK + lkq*4)*4,
                     &Asrc[(m0 + m)*K + k0 + lkq*4], true);
            }
            #pragma unroll
            for (int i = 0; i < BN/64; ++i) {
                uint32_t n = lm + i*64;
                bool ok = !GUARD || (n0 + n) < N;
                cp16(sB + (n*PK + lkq*4)*4,
                     &Bsrc[(n0 + n)*K + k0 + lkq*4], ok);
            }
        }
        CP_COMMIT();
    };
    auto compute = [&](int buf) {
        const uint32_t* A32 = reinterpret_cast<const uint32_t*>(&sm[buf][0]);
        const uint32_t* B32 = A32 + ASZ;
        #pragma unroll
        for (int g = 0; g < 2; ++g) {
            int kb = g*8 + t4;
            uint32_t af[TM][4], bf[4][2];
            #pragma unroll
            for (int tm = 0; tm < TM; ++tm) {
                int row = mbase + tm*16 + r;
                af[tm][0] = A32[row*PK + kb];
                af[tm][1] = A32[(row+8)*PK + kb];
                af[tm][2] = A32[row*PK + kb + 4];
                af[tm][3] = A32[(row+8)*PK + kb + 4];
            }
            #pragma unroll
            for (int tn = 0; tn < 4; ++tn) {
                int col = nbase + tn*8 + r;
                bf[tn][0] = B32[col*PK + kb];
                bf[tn][1] = B32[col*PK + kb + 4];
            }
            #pragma unroll
            for (int tm = 0; tm < TM; ++tm)
                #pragma unroll
                for (int tn = 0; tn < 4; ++tn)
                    mma8(acc[tm][tn], af[tm], bf[tn]);
        }
    };

    issue_tile(0);
    issue_tile(1);
    #pragma unroll 1
    for (int t = 0; t < NTILES; ++t) {
        CP_WAIT1();
        __syncthreads();
        issue_tile(t + 2);
        compute(t % 3);
    }

    // ---- epilogue ----
    if constexpr (OP == 0) {
        float* rs_ = sred;
        float* rq_ = sred + 256;
        float* s_mean = sred + 512;
        float* s_rstd = sred + 640;
        float ps[4], pq[4];
        #pragma unroll
        for (int tm = 0; tm < 2; ++tm)
            #pragma unroll
            for (int h = 0; h < 2; ++h) {
                float s = 0.f, q = 0.f;
                #pragma unroll
                for (int tn = 0; tn < 4; ++tn)
                    #pragma unroll
                    for (int e = 0; e < 2; ++e) {
                        float v = acc[tm][tn][h*2 + e];
                        s += v; q += v*v;
                    }
                ps[tm*2 + h] = s; pq[tm*2 + h] = q;
            }
        #pragma unroll
        for (int o = 1; o < 4; o <<= 1) {
            #pragma unroll
            for (int i = 0; i < 4; ++i) {
                ps[i] += __shfl_xor_sync(0xffffffff, ps[i], o);
                pq[i] += __shfl_xor_sync(0xffffffff, pq[i], o);
            }
        }
        if (t4 == 0) {
            #pragma unroll
            for (int tm = 0; tm < 2; ++tm)
                #pragma unroll
                for (int h = 0; h < 2; ++h) {
                    int row = mbase + tm*16 + r + h*8;
                    rs_[wn*128 + row] = ps[tm*2 + h];
                    rq_[wn*128 + row] = pq[tm*2 + h];
                }
        }
        __syncthreads();
        if (tid < 128) {
            float S = rs_[tid] + rs_[128 + tid];
            float Q = rq_[tid] + rq_[128 + tid];
            float mn = S * (1.f/64.f);
            float var = Q * (1.f/64.f) - mn*mn;
            s_mean[tid] = mn; s_rstd[tid] = rsqrtf(var + 1e-5f);
        }
        __syncthreads();
        #pragma unroll
        for (int tm = 0; tm < 2; ++tm)
            #pragma unroll
            for (int tn = 0; tn < 4; ++tn)
                #pragma unroll
                for (int h = 0; h < 2; ++h) {
                    int row = mbase + tm*16 + r + h*8;
                    uint32_t m = m0 + row;
                    int n = nbase + tn*8 + t4*2;
                    float2 o;
                    o.x = (acc[tm][tn][h*2+0] - s_mean[row]) * s_rstd[row]
                          * bias[n]   + aux[n];
                    o.y = (acc[tm][tn][h*2+1] - s_mean[row]) * s_rstd[row]
                          * bias[n+1] + aux[n+1];
                    *reinterpret_cast<float2*>(&g_lnb[m*64u + n]) = o;
                }
    } else {
        float cs[4][2], cq[4][2];
        if constexpr (OP == 4) {
            #pragma unroll
            for (int tn = 0; tn < 4; ++tn) {
                cs[tn][0] = cs[tn][1] = 0.f;
                cq[tn][0] = cq[tn][1] = 0.f;
            }
        }
        #pragma unroll
        for (int tm = 0; tm < TM; ++tm) {
            #pragma unroll
            for (int tn = 0; tn < 4; ++tn) {
                #pragma unroll
                for (int h = 0; h < 2; ++h) {
                    uint32_t m = m0 + mbase + tm*16 + r + h*8;
                    uint32_t n = n0 + nbase + tn*8 + t4*2;
                    if (GUARD && n >= N) continue;
                    float v0 = acc[tm][tn][h*2+0];
                    float v1 = acc[tm][tn][h*2+1];
                    if (OP == 1) {
                        float2 o = make_float2(v0, v1);
                        if (n < 128)
                            *reinterpret_cast<float2*>(&g_xc[m*128u + n]) = o;
                        else
                            *reinterpret_cast<float2*>(&g_z[m*128u + n - 128]) = o;
                    } else if (OP == 5) {
                        if (n < 32) {
                            *reinterpret_cast<float2*>(&g_bc[m*32u + n]) =
                                make_float2(v0, v1);
                        } else {
                            int col = n - 32;
                            float a0 = v0 + bias[col];
                            float a1 = v1 + bias[col+1];
                            float2 o;
                            o.x = (a0 > 20.f) ? a0 : log1pf(expf(a0));
                            o.y = (a1 > 20.f) ? a1 : log1pf(expf(a1));
                            *reinterpret_cast<float2*>(&g_dt[m*128u + col]) = o;
                        }
                    } else { // OP == 4
                        float2 o = make_float2(v0 + bias[n], v1 + bias[n+1]);
                        *reinterpret_cast<float2*>(&g_cv[m*256u + n]) = o;
                        cs[tn][0] += o.x; cq[tn][0] += o.x*o.x;
                        cs[tn][1] += o.y; cq[tn][1] += o.y*o.y;
                    }
                }
            }
        }
        if constexpr (OP == 4) {
            #pragma unroll
            for (int tn = 0; tn < 4; ++tn)
                #pragma unroll
                for (int e = 0; e < 2; ++e) {
                    float s = cs[tn][e], q = cq[tn][e];
                    #pragma unroll
                    for (int o = 4; o <= 16; o <<= 1) {
                        s += __shfl_xor_sync(0xffffffff, s, o);
                        q += __shfl_xor_sync(0xffffffff, q, o);
                    }
                    if (r == 0) {
                        int col = nbase + tn*8 + t4*2 + e;
                        sred[wm*128 + col] = s;
                        sred[256 + wm*128 + col] = q;
                    }
                }
            __syncthreads();
            if (tid < 128) {
                uint32_t gcol = n0 + tid;
                g_ps[blockIdx.y*256u + gcol] = sred[tid] + sred[128 + tid];
                g_pq[blockIdx.y*256u + gcol] = sred[256 + tid] + sred[384 + tid];
            }
        }
    }
}

// ---------------- fused MLP v2 (phase-2 k-tile widened to 32) ----------------
__global__ void __launch_bounds__(256, 2)
k_mlp2(const float* __restrict__ w1, const float* __restrict__ b1,
       const float* __restrict__ w2, const float* __restrict__ b2,
       const float* __restrict__ skp) {
    extern __shared__ float dsm[];
    constexpr int PIPE = (64 + 128) * 20;   // 3840 floats (>= 64*36 = 2304)
    float* Pb = dsm;
    float* Hs = dsm + 2*PIPE;

    int tid = threadIdx.x;
    int lane = tid & 31, w = tid >> 5;
    int r = lane >> 2, t4 = lane & 3;
    int wm = w & 1, wn = w >> 1;
    int lm = tid >> 2, lkq = tid & 3;
    float sk = skp[0];
    uint32_t m0 = blockIdx.y * 64;
    const uint32_t* Hu = reinterpret_cast<const uint32_t*>(Hs);

    #pragma unroll 1
    for (int nb = 0; nb < 2; ++nb) {
        float acc[2][4][4] = {};
        auto issue1 = [&](int t) {
            if (t < 4) {
                uint32_t sA = (uint32_t)__cvta_generic_to_shared(&Pb[(t & 1)*PIPE]);
                uint32_t sB = sA + 64*20*4;
                cp16(sA + (lm*20 + lkq*4)*4,
                     &g_lnb[(m0 + lm)*64u + t*16 + lkq*4], true);
                #pragma unroll
                for (int i = 0; i < 2; ++i) {
                    int n = lm + i*64;
                    cp16(sB + (n*20 + lkq*4)*4,
                         &w1[(nb*128 + n)*64u + t*16 + lkq*4], true);
                }
            }
            CP_COMMIT();
        };
        issue1(0);
        #pragma unroll 1
        for (int t = 0; t < 4; ++t) {
            issue1(t + 1);
            CP_WAIT1();
            __syncthreads();
            const uint32_t* A32 = reinterpret_cast<const uint32_t*>(&Pb[(t & 1)*PIPE]);
            const uint32_t* B32 = A32 + 64*20;
            #pragma unroll
            for (int g = 0; g < 2; ++g) {
                int kb = g*8 + t4;
                uint32_t af[2][4], bf[4][2];
                #pragma unroll
                for (int tm = 0; tm < 2; ++tm) {
                    int row = wm*32 + tm*16 + r;
                    af[tm][0] = A32[row*20 + kb];
                    af[tm][1] = A32[(row+8)*20 + kb];
                    af[tm][2] = A32[row*20 + kb + 4];
                    af[tm][3] = A32[(row+8)*20 + kb + 4];
                }
                #pragma unroll
                for (int tn = 0; tn < 4; ++tn) {
                    int col = wn*32 + tn*8 + r;
                    bf[tn][0] = B32[col*20 + kb];
                    bf[tn][1] = B32[col*20 + kb + 4];
                }
                #pragma unroll
                for (int tm = 0; tm < 2; ++tm)
                    #pragma unroll
                    for (int tn = 0; tn < 4; ++tn)
                        mma8(acc[tm][tn], af[tm], bf[tn]);
            }
            __syncthreads();
        }
        #pragma unroll
        for (int tm = 0; tm < 2; ++tm)
            #pragma unroll
            for (int tn = 0; tn < 4; ++tn)
                #pragma unroll
                for (int h = 0; h < 2; ++h) {
                    int row = wm*32 + tm*16 + r + h*8;
                    int col = nb*128 + wn*32 + tn*8 + t4*2;
                    float2 o;
                    o.x = gelu_exact(acc[tm][tn][h*2+0] + b1[col]);
                    o.y = gelu_exact(acc[tm][tn][h*2+1] + b1[col+1]);
                    *reinterpret_cast<float2*>(&Hs[row*260 + col]) = o;
                }
    }
    __syncthreads();

    // phase 2: out = H @ W2^T, k-tile = 32 (pitch 36; 8 iterations)
    float acc2[2][2][4] = {};
    int lm8 = tid >> 3, lk8 = tid & 7;      // 32 rows/iter loader coords
    auto issue2 = [&](int t) {
        if (t < 8) {
            uint32_t sB = (uint32_t)__cvta_generic_to_shared(&Pb[(t & 1)*PIPE]);
            #pragma unroll
            for (int i = 0; i < 2; ++i) {
                int row = lm8 + i*32;
                cp16(sB + (row*36 + lk8*4)*4,
                     &w2[row*256u + t*32 + lk8*4], true);
            }
        }
        CP_COMMIT();
    };
    issue2(0);
    #pragma unroll 1
    for (int t = 0; t < 8; ++t) {
        issue2(t + 1);
        CP_WAIT1();
        __syncthreads();
        const uint32_t* B32 = reinterpret_cast<const uint32_t*>(&Pb[(t & 1)*PIPE]);
        #pragma unroll
        for (int g = 0; g < 4; ++g) {
            int kb = g*8 + t4;
            int kg = t*32 + kb;
            uint32_t af[2][4], bf[2][2];
            #pragma unroll
            for (int tm = 0; tm < 2; ++tm) {
                int row = wm*32 + tm*16 + r;
                af[tm][0] = Hu[row*260 + kg];
                af[tm][1] = Hu[(row+8)*260 + kg];
                af[tm][2] = Hu[row*260 + kg + 4];
                af[tm][3] = Hu[(row+8)*260 + kg + 4];
            }
            #pragma unroll
            for (int tn = 0; tn < 2; ++tn) {
                int col = wn*16 + tn*8 + r;
                bf[tn][0] = B32[col*36 + kb];
                bf[tn][1] = B32[col*36 + kb + 4];
            }
            #pragma unroll
            for (int tm = 0; tm < 2; ++tm)
                #pragma unroll
                for (int tn = 0; tn < 2; ++tn)
                    mma8(acc2[tm][tn], af[tm], bf[tn]);
        }
        __syncthreads();
    }
    #pragma unroll
    for (int tm = 0; tm < 2; ++tm)
        #pragma unroll
        for (int tn = 0; tn < 2; ++tn)
            #pragma unroll
            for (int h = 0; h < 2; ++h) {
                int row = wm*32 + tm*16 + r + h*8;
                int col = wn*16 + tn*8 + t4*2;
                uint32_t m = m0 + row;
                float2 o;
                o.x = acc2[tm][tn][h*2+0] + b2[col]   + sk * g_xi[m*64u + col];
                o.y = acc2[tm][tn][h*2+1] + b2[col+1] + sk * g_xi[m*64u + col + 1];
                uint32_t l = m & (LQ-1);
                uint32_t nb2 = m >> 12;
                uint32_t chunk = nb2 >> 3, b = nb2 & 7;
                *reinterpret_cast<float2*>(
                    &g_inter[((b*LQ + l)*256u) + chunk*64 + col]) = o;
            }
}

// ---------------- depthwise causal conv1d(4) + bias + silu ----------------
__global__ void k_conv_silu(const float* __restrict__ cw,
                            const float* __restrict__ cb) {
    size_t id = (size_t)blockIdx.x * 256 + threadIdx.x;
    int d = id & 127;
    size_t q = id >> 7;
    int lg = (int)(q & 1023);
    size_t n = q >> 10;
    int l0 = lg * 4;
    const float* base = g_xc + ((n*LQ) << 7) + d;
    float w0 = cw[d*4], w1 = cw[d*4+1], w2 = cw[d*4+2], w3 = cw[d*4+3];
    float b = cb[d];
    float xv[7];
    #pragma unroll
    for (int t = 0; t < 7; ++t) {
        int ll = l0 - 3 + t;
        xv[t] = (ll >= 0) ? base[(size_t)ll*128] : 0.f;
    }
    float* outp = g_u + ((n*LQ) << 7) + ((size_t)l0 << 7) + d;
    #pragma unroll
    for (int i = 0; i < 4; ++i) {
        float acc = b;
        acc = fmaf(xv[i],   w0, acc);
        acc = fmaf(xv[i+1], w1, acc);
        acc = fmaf(xv[i+2], w2, acc);
        acc = fmaf(xv[i+3], w3, acc);
        float sig = 1.f / (1.f + __expf(-acc));
        outp[(size_t)i*128] = acc * sig;
    }
}

// ---------------- scan phase 1 ----------------
__global__ void k_scan1() {
    int blk = blockIdx.x;
    int n = blk >> 5;
    int g = blk & 31;
    int d = threadIdx.x;
    int fast = g_fastA;
    float A0 = g_Aa[d*DS];
    float A[DS], h[DS];
    #pragma unroll
    for (int s = 0; s < DS; ++s) { A[s] = g_Aa[d*DS + s]; h[s] = 0.f; }
    float dtsum = 0.f;
    __shared__ __align__(16) float sBC[16*32];
    size_t l0 = (size_t)g * CLEN;
    size_t base = ((size_t)n * LQ) * 128;
    for (int t0 = 0; t0 < CLEN; t0 += 16) {
        reinterpret_cast<float4*>(sBC)[d] =
            reinterpret_cast<const float4*>(g_bc + ((size_t)n*LQ + l0 + t0)*32)[d];
        __syncthreads();
        for (int st = 0; st < 16; ++st) {
            size_t l = l0 + t0 + st;
            float dt = g_dt[base + l*128 + d];
            float uu = g_u [base + l*128 + d];
            float du = dt * uu;
            dtsum += dt;
            const float* Bl = &sBC[st*32];
            if (fast) {
                float p = __expf(dt * A0);
                float a = 1.f;
                #pragma unroll
                for (int s = 0; s < DS; ++s) {
                    a *= p;
                    h[s] = fmaf(a, h[s], du * Bl[s]);
                }
            } else {
                #pragma unroll
                for (int s = 0; s < DS; ++s) {
                    float a = __expf(dt * A[s]);
                    h[s] = fmaf(a, h[s], du * Bl[s]);
                }
            }
        }
        __syncthreads();
    }
    size_t off = (((size_t)(n*NCH + g))*128 + d)*DS;
    if (fast) {
        float p = __expf(dtsum * A0);
        float a = 1.f;
        #pragma unroll
        for (int s = 0; s < DS; ++s) { a *= p; g_P[off + s] = a; g_hend[off + s] = h[s]; }
    } else {
        #pragma unroll
        for (int s = 0; s < DS; ++s) {
            g_P[off + s] = __expf(A[s] * dtsum);
            g_hend[off + s] = h[s];
        }
    }
}

// ---------------- scan phase 2 ----------------
__global__ void k_scan2() {
    int lane = blockIdx.x * 256 + threadIdx.x;
    int s = lane & 15;
    int d = (lane >> 4) & 127;
    int n = lane >> 11;
    float h = 0.f;
    for (int g = 0; g < NCH; ++g) {
        size_t off = (((size_t)(n*NCH + g))*128 + d)*DS + s;
        g_hin[off] = h;
        h = g_P[off]*h + g_hend[off];
    }
}

// ---------------- scan phase 3 ----------------
__global__ void k_scan3(const float* __restrict__ Dp) {
    int blk = blockIdx.x;
    int n = blk >> 5;
    int g = blk & 31;
    int d = threadIdx.x;
    int fast = g_fastA;
    float A0 = g_Aa[d*DS];
    float A[DS], h[DS];
    size_t off = (((size_t)(n*NCH + g))*128 + d)*DS;
    #pragma unroll
    for (int s = 0; s < DS; ++s) { A[s] = g_Aa[d*DS + s]; h[s] = g_hin[off + s]; }
    float Dd = Dp[d];
    __shared__ __align__(16) float sBC[16*32];
    size_t l0 = (size_t)g * CLEN;
    size_t base = ((size_t)n * LQ) * 128;
    for (int t0 = 0; t0 < CLEN; t0 += 16) {
        reinterpret_cast<float4*>(sBC)[d] =
            reinterpret_cast<const float4*>(g_bc + ((size_t)n*LQ + l0 + t0)*32)[d];
        __syncthreads();
        for (int st = 0; st < 16; ++st) {
            size_t l = l0 + t0 + st;
            float dt = g_dt[base + l*128 + d];
            float uu = g_u [base + l*128 + d];
            float zz = g_z [base + l*128 + d];
            float du = dt * uu;
            const float* Bl = &sBC[st*32];
            const float* Cl = Bl + 16;
            float y = 0.f;
            if (fast) {
                float p = __expf(dt * A0);
                float a = 1.f;
                #pragma unroll
                for (int s = 0; s < DS; ++s) {
                    a *= p;
                    h[s] = fmaf(a, h[s], du * Bl[s]);
                    y = fmaf(h[s], Cl[s], y);
                }
            } else {
                #pragma unroll
                for (int s = 0; s < DS; ++s) {
                    float a = __expf(dt * A[s]);
                    h[s] = fmaf(a, h[s], du * Bl[s]);
                    y = fmaf(h[s], Cl[s], y);
                }
            }
            y += uu * Dd;
            float sz = zz / (1.f + __expf(-zz));
            g_y[base + l*128 + d] = y * sz;
        }
        __syncthreads();
    }
}

// ---------------- BN finalize ----------------
__global__ void k_bnfin(const float* __restrict__ gamma,
                        const float* __restrict__ beta) {
    int o = threadIdx.x;
    float s = 0.f, q = 0.f;
    for (int k = 0; k < 256; ++k) { s += g_ps[k*256 + o]; q += g_pq[k*256 + o]; }
    float mean = s * (1.f/32768.f);
    float var  = q * (1.f/32768.f) - mean*mean;
    float rg = rsqrtf(var + 1e-5f) * gamma[o];
    g_bnA[o] = rg;
    g_bnB[o] = beta[o] - mean*rg;
}

// ---------------- transpose + BN + relu ----------------
__global__ void k_out(float* __restrict__ out) {
    int bid = blockIdx.x;
    int lg = bid & 127;
    int og = (bid >> 7) & 7;
    int b  = bid >> 10;
    __shared__ float tile[32][33];
    int tid = threadIdx.x;
    int o_in = tid & 31;
    int l_in = tid >> 5;
    size_t l0 = (size_t)lg * 32, o0 = (size_t)og * 32;
    float a = g_bnA[o0 + o_in], c = g_bnB[o0 + o_in];
    #pragma unroll
    for (int i = 0; i < 4; ++i) {
        int l = l_in + i*8;
        float v = g_cv[((size_t)b*LQ + l0 + l)*256 + o0 + o_in];
        tile[l][o_in] = v*a + c;
    }
    __syncthreads();
    int l_out = tid & 31;
    int o_off = tid >> 5;
    #pragma unroll
    for (int i = 0; i < 4; ++i) {
        int o = o_off + i*8;
        out[((size_t)(b*256 + o0 + o))*LQ + l0 + l_out] = fmaxf(tile[l_out][o], 0.f);
    }
}

// ---------------- launcher ----------------
extern "C" void kernel_launch(void* const* d_in, const int* in_sizes, int n_in,
                              void* d_out, int out_size) {
    const float* x         = (const float*)d_in[0];
    const float* norm_w    = (const float*)d_in[1];
    const float* norm_b    = (const float*)d_in[2];
    const float* norm1_w   = (const float*)d_in[3];
    const float* norm1_b   = (const float*)d_in[4];
    const float* in_proj_w = (const float*)d_in[5];
    const float* conv_w    = (const float*)d_in[6];
    const float* conv_b    = (const float*)d_in[7];
    const float* x_proj_w  = (const float*)d_in[8];
    const float* dt_w      = (const float*)d_in[9];
    const float* dt_b      = (const float*)d_in[10];
    const float* A_log     = (const float*)d_in[11];
    const float* D_param   = (const float*)d_in[12];
    const float* out_proj_w= (const float*)d_in[13];
    const float* fc1_w     = (const float*)d_in[14];
    const float* fc1_b     = (const float*)d_in[15];
    const float* fc2_w     = (const float*)d_in[16];
    const float* fc2_b     = (const float*)d_in[17];
    const float* skip      = (const float*)d_in[18];
    const float* oc_w      = (const float*)d_in[19];
    const float* oc_b      = (const float*)d_in[20];
    const float* gamma     = (const float*)d_in[21];
    const float* beta      = (const float*)d_in[22];
    float* out = (float*)d_out;

    const int MLP_SMEM = (2*(64+128)*20 + 64*260) * 4;
    cudaFuncSetAttribute(k_mlp2, cudaFuncAttributeMaxDynamicSharedMemorySize, MLP_SMEM);

    k_prep<<<256, 256>>>(A_log, oc_w, x_proj_w, dt_w);
    k_checkA<<<1, 256>>>();
    k_ln_split<<<1024, 256>>>(x, norm_w, norm_b);
    k_gemm<1><<<dim3(2, M1/128), 256>>>(in_proj_w,  nullptr, nullptr);
    k_conv_silu<<<16384, 256>>>(conv_w, conv_b);
    k_gemm<5><<<dim3(3, M1/128), 256>>>(nullptr,    dt_b, nullptr);
    k_scan1<<<NBAT*NCH, 128>>>();
    k_scan2<<<256, 256>>>();
    k_scan3<<<NBAT*NCH, 128>>>(D_param);
    k_gemm<0><<<dim3(1, M1/128), 256>>>(out_proj_w, norm1_w, norm1_b);
    k_mlp2<<<dim3(1, M1/64), 256, MLP_SMEM>>>(fc1_w, fc1_b, fc2_w, fc2_b, skip);
    k_gemm<4><<<dim3(2, M2/128), 256>>>(nullptr,    oc_b, nullptr);
    k_bnfin<<<1, 256>>>(gamma, beta);
    k_out<<<8192, 256>>>(out);
}